// round 9
// baseline (speedup 1.0000x reference)
#include <cuda_runtime.h>
#include <cuda_fp16.h>
#include <math.h>
#include <stdint.h>

#define BATCH 64
#define SEQ   512
#define EMB   256
#define HID   512
#define G4    2048   // 4*HID
#define NCLS  4
#define NCTA  128    // persistent CTAs, one per SM
#define HPAD  68     // fp32 pad stride (xg_gemm frags, pre)
#define KPADH 520    // fp16 row stride (halves): 512 + 8 -> 4-bank row offset

// Scratch (allocation-free rule: __device__ globals)
__device__ float  g_xg[(size_t)SEQ * G4 * BATCH];  // [t][n][b], n = gate*H + j
__device__ __half g_h[2][BATCH * HID];             // [buf][b][k]  fp16
__device__ unsigned int g_bar;
__device__ unsigned int g_epoch;

__device__ __forceinline__ float sigmoidf_(float x) {
    return 1.0f / (1.0f + __expf(-x));
}
__device__ __forceinline__ uint32_t f2tf32(float f) {
    uint32_t u;
    asm("cvt.rna.tf32.f32 %0, %1;" : "=r"(u) : "f"(f));
    return u;
}
__device__ __forceinline__ void mma_tf32(float& d0, float& d1, float& d2, float& d3,
                                         uint32_t a0, uint32_t a1, uint32_t a2, uint32_t a3,
                                         uint32_t b0, uint32_t b1) {
    asm volatile("mma.sync.aligned.m16n8k8.row.col.f32.tf32.tf32.f32 "
                 "{%0,%1,%2,%3}, {%4,%5,%6,%7}, {%8,%9}, {%0,%1,%2,%3};"
                 : "+f"(d0), "+f"(d1), "+f"(d2), "+f"(d3)
                 : "r"(a0), "r"(a1), "r"(a2), "r"(a3), "r"(b0), "r"(b1));
}
__device__ __forceinline__ void mma_f16(float& d0, float& d1, float& d2, float& d3,
                                        uint32_t a0, uint32_t a1, uint32_t a2, uint32_t a3,
                                        uint32_t b0, uint32_t b1) {
    asm volatile("mma.sync.aligned.m16n8k16.row.col.f32.f16.f16.f32 "
                 "{%0,%1,%2,%3}, {%4,%5,%6,%7}, {%8,%9}, {%0,%1,%2,%3};"
                 : "+f"(d0), "+f"(d1), "+f"(d2), "+f"(d3)
                 : "r"(a0), "r"(a1), "r"(a2), "r"(a3), "r"(b0), "r"(b1));
}

// cp.async.cg: 16B global->shared, L1-bypass.
__device__ __forceinline__ void cp_async16(void* smem_dst, const void* gmem_src) {
    unsigned saddr = (unsigned)__cvta_generic_to_shared(smem_dst);
    asm volatile("cp.async.cg.shared.global [%0], [%1], 16;"
                 :: "r"(saddr), "l"(gmem_src) : "memory");
}
__device__ __forceinline__ void cp_async_commit() {
    asm volatile("cp.async.commit_group;" ::: "memory");
}
template <int N>
__device__ __forceinline__ void cp_async_wait() {
    asm volatile("cp.async.wait_group %0;" :: "n"(N) : "memory");
}

__global__ void init_state() {
    int i = blockIdx.x * blockDim.x + threadIdx.x;   // 32768 threads
    ((uint32_t*)g_h)[i] = 0u;                        // zero both h buffers (fp16x2)
    if (i == 0) { g_bar = 0u; g_epoch = 0u; }
}

// ============================================================================
// xg_gemm (tf32 mma, proven R8): xg[t][n][b] = emb[tok] @ W_ih^T + bias
// ============================================================================
__global__ void __launch_bounds__(256)
xg_gemm(const int* __restrict__ x, const float* __restrict__ emb,
        const float* __restrict__ W_ih,
        const float* __restrict__ b_ih, const float* __restrict__ b_hh) {
    __shared__ float As[32][HPAD];
    __shared__ float Bs[32][HPAD];
    __shared__ int   tok_s[64];
    __shared__ float sbias[64];

    const int t    = blockIdx.y;
    const int ncta = blockIdx.x * 64;
    const int tid  = threadIdx.x;
    const int warp = tid >> 5;
    const int lane = tid & 31;
    const int gid  = lane >> 2;
    const int tig  = lane & 3;
    const int wm   = warp & 3;
    const int wn   = warp >> 2;
    const int m0   = wm * 16;

    if (tid < 64) {
        tok_s[tid] = x[tid * SEQ + t];
        int n = ncta + tid;
        sbias[tid] = b_ih[n] + b_hh[n];
    }
    __syncthreads();

    const uint32_t* Asu = (const uint32_t*)As;
    const uint32_t* Bsu = (const uint32_t*)Bs;

    float d[4][4] = {};

    for (int kt = 0; kt < EMB; kt += 32) {
        #pragma unroll
        for (int jj = 0; jj < 2; jj++) {
            int idx = tid + jj * 256;
            int row = idx >> 3, qk = idx & 7;
            float4 av = *(const float4*)(emb + (size_t)tok_s[row] * EMB + kt + qk * 4);
            As[qk*4+0][row] = __uint_as_float(f2tf32(av.x));
            As[qk*4+1][row] = __uint_as_float(f2tf32(av.y));
            As[qk*4+2][row] = __uint_as_float(f2tf32(av.z));
            As[qk*4+3][row] = __uint_as_float(f2tf32(av.w));
            float4 bv = *(const float4*)(W_ih + (size_t)(ncta + row) * EMB + kt + qk * 4);
            Bs[qk*4+0][row] = __uint_as_float(f2tf32(bv.x));
            Bs[qk*4+1][row] = __uint_as_float(f2tf32(bv.y));
            Bs[qk*4+2][row] = __uint_as_float(f2tf32(bv.z));
            Bs[qk*4+3][row] = __uint_as_float(f2tf32(bv.w));
        }
        __syncthreads();

        #pragma unroll
        for (int s = 0; s < 4; s++) {
            const int k0 = s * 8;
            uint32_t a0 = Asu[(k0 + tig)     * HPAD + m0 + gid];
            uint32_t a1 = Asu[(k0 + tig)     * HPAD + m0 + gid + 8];
            uint32_t a2 = Asu[(k0 + tig + 4) * HPAD + m0 + gid];
            uint32_t a3 = Asu[(k0 + tig + 4) * HPAD + m0 + gid + 8];
            #pragma unroll
            for (int nt = 0; nt < 4; nt++) {
                const int n0 = wn * 32 + nt * 8;
                uint32_t b0 = Bsu[(k0 + tig)     * HPAD + n0 + gid];
                uint32_t b1 = Bsu[(k0 + tig + 4) * HPAD + n0 + gid];
                mma_tf32(d[nt][0], d[nt][1], d[nt][2], d[nt][3],
                         a0, a1, a2, a3, b0, b1);
            }
        }
        __syncthreads();
    }

    #pragma unroll
    for (int nt = 0; nt < 4; nt++) {
        const int na = wn * 32 + nt * 8 + 2 * tig;
        const int nb = na + 1;
        const int r0 = m0 + gid;
        const int r1 = r0 + 8;
        g_xg[((size_t)t * G4 + ncta + na) * BATCH + r0] = d[nt][0] + sbias[na];
        g_xg[((size_t)t * G4 + ncta + nb) * BATCH + r0] = d[nt][1] + sbias[nb];
        g_xg[((size_t)t * G4 + ncta + na) * BATCH + r1] = d[nt][2] + sbias[na];
        g_xg[((size_t)t * G4 + ncta + nb) * BATCH + r1] = d[nt][3] + sbias[nb];
    }
}

// ============================================================================
// Persistent recurrence, fp16 mma m16n8k16. 128 CTAs x 512 threads (16 warps).
// h stored [b][k] fp16 in gmem and smem (KPADH stride). Warp = wm(4) x wn(2)
// x kh(2 split-K). Single-shot 64KB h broadcast via cp.async.
// ============================================================================
__global__ void __launch_bounds__(512, 1)
lstm_persistent(const float* __restrict__ W_hh) {
    extern __shared__ __align__(16) char smraw[];
    __half* h_s = (__half*)smraw;                        // [64][KPADH]
    __half* W_s = h_s + BATCH * KPADH;                   // [16][KPADH]
    float*  pre = (float*)(W_s + 16 * KPADH);            // [32][HPAD] fp32

    const int tid  = threadIdx.x;             // 512
    const int cta  = blockIdx.x;
    const int warp = tid >> 5;
    const int lane = tid & 31;
    const int gid  = lane >> 2;
    const int tig  = lane & 3;
    const int wm   = warp & 3;                // m0 = wm*16
    const int wn   = (warp >> 2) & 1;         // n0 = wn*8
    const int kh   = warp >> 3;               // split-K half
    const int m0   = wm * 16;
    const int n0   = wn * 8;
    const int j0   = cta * 4;

    // One-time: 16 W_hh rows -> smem fp16.
    #pragma unroll
    for (int row = 0; row < 16; row++) {
        int g = row >> 2, u = row & 3;
        W_s[row * KPADH + tid] = __float2half_rn(
            W_hh[(size_t)(g * HID + j0 + u) * HID + tid]);
    }
    float c_reg = 0.0f;
    __syncthreads();

    const uint32_t* Hs32 = (const uint32_t*)h_s;
    const uint32_t* Ws32 = (const uint32_t*)W_s;
    const int eb = tid & 63;          // epilogue batch
    const int eu = (tid >> 6) & 3;    // epilogue unit

    for (int t = 0; t < SEQ; t++) {
        const int rb = t & 1;
        const char* hsrc = (const char*)g_h[rb];

        // Issue full 64KB h broadcast: 4096 x 16B / 512 thr = 8 each.
        #pragma unroll
        for (int i = 0; i < 8; i++) {
            int p = tid + i * 512;                 // 16B piece
            int b = p >> 6, sub = p & 63;
            cp_async16(h_s + b * KPADH + sub * 8, hsrc + p * 16);
        }
        cp_async_commit();

        // Prefetch xg (epilogue threads) — overlaps the copy.
        float xi = 0.f, xf = 0.f, xG = 0.f, xo = 0.f;
        if (tid < 256) {
            const float* xg = g_xg + ((size_t)t * G4 + j0 + eu) * BATCH + eb;
            xi = __ldcg(xg + 0 * HID * BATCH);
            xf = __ldcg(xg + 1 * HID * BATCH);
            xG = __ldcg(xg + 2 * HID * BATCH);
            xo = __ldcg(xg + 3 * HID * BATCH);
        }

        cp_async_wait<0>();
        __syncthreads();

        float d0 = 0.f, d1 = 0.f, d2 = 0.f, d3 = 0.f;
        const int rA0 = (m0 + gid) * 260;          // word-stride 520/2
        const int rA1 = (m0 + gid + 8) * 260;
        const int rB  = (n0 + gid) * 260;
        #pragma unroll
        for (int s = 0; s < 16; s++) {
            const int KW = kh * 128 + s * 8;       // word offset of k0
            uint32_t a0 = Hs32[rA0 + KW + tig];
            uint32_t a1 = Hs32[rA1 + KW + tig];
            uint32_t a2 = Hs32[rA0 + KW + tig + 4];
            uint32_t a3 = Hs32[rA1 + KW + tig + 4];
            uint32_t b0 = Ws32[rB + KW + tig];
            uint32_t b1 = Ws32[rB + KW + tig + 4];
            mma_f16(d0, d1, d2, d3, a0, a1, a2, a3, b0, b1);
        }

        // Split-K partials: pre[kh*16 + n][b].
        {
            const int na = n0 + 2 * tig;
            const int r0 = m0 + gid;
            pre[(kh * 16 + na)     * HPAD + r0]     = d0;
            pre[(kh * 16 + na + 1) * HPAD + r0]     = d1;
            pre[(kh * 16 + na)     * HPAD + r0 + 8] = d2;
            pre[(kh * 16 + na + 1) * HPAD + r0 + 8] = d3;
        }
        __syncthreads();

        if (tid < 256) {
            const int b = eb, u = eu;
            float ai = pre[(0 * 4 + u) * HPAD + b] + pre[(16 + 0 * 4 + u) * HPAD + b];
            float af = pre[(1 * 4 + u) * HPAD + b] + pre[(16 + 1 * 4 + u) * HPAD + b];
            float ag = pre[(2 * 4 + u) * HPAD + b] + pre[(16 + 2 * 4 + u) * HPAD + b];
            float ao = pre[(3 * 4 + u) * HPAD + b] + pre[(16 + 3 * 4 + u) * HPAD + b];

            float gi = sigmoidf_(ai + xi);
            float gf = sigmoidf_(af + xf);
            float gG = tanhf   (ag + xG);
            float go = sigmoidf_(ao + xo);
            c_reg = gf * c_reg + gi * gG;
            float hv = go * tanhf(c_reg);

            unsigned short hbits = __half_as_ushort(__float2half_rn(hv));
            asm volatile("st.global.cg.b16 [%0], %1;"
                         :: "l"(&g_h[rb ^ 1][(size_t)b * HID + j0 + u]), "h"(hbits)
                         : "memory");
        }

        // Grid barrier: fence+arrive by tid0 only; leader releases epoch.
        __syncthreads();
        if (tid == 0) {
            __threadfence();
            unsigned a = atomicAdd(&g_bar, 1u) + 1u;
            const unsigned tgt = (unsigned)(t + 1) * NCTA;
            if (a == tgt) {
                asm volatile("st.release.gpu.global.u32 [%0], %1;"
                             :: "l"(&g_epoch), "r"(tgt) : "memory");
            } else {
                unsigned v;
                do {
                    asm volatile("ld.acquire.gpu.global.u32 %0, [%1];"
                                 : "=r"(v) : "l"(&g_epoch) : "memory");
                } while (v < tgt);
            }
            __threadfence();
        }
        __syncthreads();
    }
}

// Final FC: warp per output element. h is fp16 [b][k]; final h in g_h[0].
__global__ void fc_kernel(const float* __restrict__ W_fc, const float* __restrict__ b_fc,
                          float* __restrict__ out) {
    const int warp = (blockIdx.x * blockDim.x + threadIdx.x) >> 5;
    const int lane = threadIdx.x & 31;
    const int b = warp >> 2, c = warp & 3;
    const __half* h0 = g_h[0] + (size_t)b * HID;
    const float* w  = W_fc + c * HID;
    float acc = 0.f;
    #pragma unroll 4
    for (int k = lane; k < HID; k += 32)
        acc += __half2float(h0[k]) * w[k];
    #pragma unroll
    for (int off = 16; off; off >>= 1)
        acc += __shfl_xor_sync(0xFFFFFFFFu, acc, off);
    if (lane == 0) out[b * NCLS + c] = acc + b_fc[c];
}

extern "C" void kernel_launch(void* const* d_in, const int* in_sizes, int n_in,
                              void* d_out, int out_size) {
    const int*   x    = (const int*)  d_in[0];
    const float* emb  = (const float*)d_in[1];
    const float* W_ih = (const float*)d_in[2];
    const float* W_hh = (const float*)d_in[3];
    const float* b_ih = (const float*)d_in[4];
    const float* b_hh = (const float*)d_in[5];
    const float* W_fc = (const float*)d_in[6];
    const float* b_fc = (const float*)d_in[7];
    float* out = (float*)d_out;

    const int smem_bytes = (BATCH * KPADH + 16 * KPADH) * 2 + 32 * HPAD * 4; // ~92 KiB
    cudaFuncSetAttribute(lstm_persistent,
                         cudaFuncAttributeMaxDynamicSharedMemorySize, smem_bytes);

    init_state<<<64, 512>>>();

    dim3 g1(G4 / 64, SEQ);   // 32 x 512 CTAs
    xg_gemm<<<g1, 256>>>(x, emb, W_ih, b_ih, b_hh);

    lstm_persistent<<<NCTA, 512, smem_bytes>>>(W_hh);

    fc_kernel<<<32, 256>>>(W_fc, b_fc, out);
}